// round 13
// baseline (speedup 1.0000x reference)
#include <cuda_runtime.h>

// Decoder: T_IN=12, B=65536, H=64, T_OUT=12, OVERLAP=3
// 256 threads / 16 batches per CTA, target 2 CTAs/SM (4 warps/SMSP).
//   Phase A: 16-lane group owns one batch (2 batches/warp), lane owns 4 dims.
//   Phase B: tf32 mma.sync.m16n8k8 — M=16 batches; warp w owns gate-aligned
//            n-tiles {w, w+8, w+16} = dims 8w..8w+7 for gates r,z,n.
// Same MMA k-decomposition as R8 -> bit-identical GRU matvec numerics.

#define FULLMASK 0xFFFFFFFFu

constexpr int T_IN  = 12;
constexpr int T_OUT = 12;
constexpr int Bz    = 65536;
constexpr int WARPS = 8;
constexpr int THREADS = WARPS * 32;
constexpr int BPC   = 16;            // batches per CTA
constexpr int HPAD  = 68;            // padded row pitch (floats) for hA/hG

// SMEM float offsets
constexpr int WFRAG_N   = 24 * 8 * 32;          // ntg x kt x lane (uint2) = 6144
constexpr int OFF_HA    = WFRAG_N * 2;          // 12288
constexpr int OFF_HG    = OFF_HA + BPC * HPAD;  // +1088
constexpr int OFF_L     = OFF_HG + BPC * HPAD;  // +1088
constexpr int OFF_GP    = OFF_L + BPC * 4;      // +64
constexpr int OFF_BH    = OFF_GP + 192 * 4;     // +768
constexpr int OFF_WL    = OFF_BH + 192;         // +192
constexpr int SMEM_FLOATS = OFF_WL + 64;
constexpr int SMEM_BYTES  = SMEM_FLOATS * 4;    // 62,208 B -> 2 CTAs/SM

__device__ __forceinline__ unsigned cvt_tf32(float x) {
    unsigned r;
    asm("cvt.rna.tf32.f32 %0, %1;" : "=r"(r) : "f"(x));
    return r;
}
__device__ __forceinline__ void mma_tf32(float& d0, float& d1, float& d2, float& d3,
                                         unsigned a0, unsigned a1, unsigned a2, unsigned a3,
                                         unsigned b0, unsigned b1) {
    asm("mma.sync.aligned.m16n8k8.row.col.f32.tf32.tf32.f32 "
        "{%0,%1,%2,%3}, {%4,%5,%6,%7}, {%8,%9}, {%0,%1,%2,%3};"
        : "+f"(d0), "+f"(d1), "+f"(d2), "+f"(d3)
        : "r"(a0), "r"(a1), "r"(a2), "r"(a3), "r"(b0), "r"(b1));
}
__device__ __forceinline__ float sigf(float x) {
    return __fdividef(1.0f, 1.0f + __expf(-x));
}
__device__ __forceinline__ float tanhfast(float x) {
    return __fdividef(2.0f, 1.0f + __expf(-2.0f * x)) - 1.0f;
}
__device__ __forceinline__ float dot4(float4 a, float4 b) {
    float s = a.x * b.x;
    s = fmaf(a.y, b.y, s); s = fmaf(a.z, b.z, s); s = fmaf(a.w, b.w, s);
    return s;
}

__global__ void __launch_bounds__(THREADS, 2)
decoder_kernel(const float* __restrict__ enc,    // (12, B, 64)
               const float* __restrict__ hid0,   // (B, 64)
               const float* __restrict__ last,   // (B, 3)
               const float* __restrict__ Wih,    // (192, 3)
               const float* __restrict__ Whh,    // (192, 64)
               const float* __restrict__ bih,    // (192)
               const float* __restrict__ bhh,    // (192)
               const float* __restrict__ Wlin,   // (1, 64)
               const float* __restrict__ blin,   // (1)
               float* __restrict__ out)          // (B, 12)
{
    extern __shared__ float smem[];
    uint2*  Wfr  = reinterpret_cast<uint2*>(smem);
    float*  hAsh = smem + OFF_HA;
    float*  hGsh = smem + OFF_HG;
    float4* Lsh  = reinterpret_cast<float4*>(smem + OFF_L);
    float4* gpsh = reinterpret_cast<float4*>(smem + OFF_GP);   // {wih0,1,2,bih}
    float*  bhsh = smem + OFF_BH;
    float*  wlsh = smem + OFF_WL;

    const int tid  = threadIdx.x;
    const int lane = tid & 31;
    const int w    = tid >> 5;
    const int cb0  = blockIdx.x * BPC;

    // ---- stage W_hh into B-fragment layout (tf32), once ----
    // Wfr[(ntg*8 + kt)*32 + ln] = {W[j][kt*8+t4], W[j][kt*8+t4+4]} (tf32)
    // ntg = w' + 8*gate; j = gate*64 + w'*8 + (ln>>2); t4 = ln&3
    for (int i = tid; i < WFRAG_N; i += THREADS) {
        int ntg = i >> 8;
        int kt  = (i >> 5) & 7;
        int ln  = i & 31;
        int gg  = ln >> 2, t4 = ln & 3;
        int j   = ((ntg >> 3) << 6) + ((ntg & 7) << 3) + gg;
        float b0 = __ldg(&Whh[j * 64 + kt * 8 + t4]);
        float b1 = __ldg(&Whh[j * 64 + kt * 8 + t4 + 4]);
        Wfr[i] = make_uint2(cvt_tf32(b0), cvt_tf32(b1));
    }
    // ---- stage params ----
    for (int j = tid; j < 192; j += THREADS) {
        gpsh[j] = make_float4(__ldg(&Wih[j * 3 + 0]), __ldg(&Wih[j * 3 + 1]),
                              __ldg(&Wih[j * 3 + 2]), __ldg(&bih[j]));
        bhsh[j] = __ldg(&bhh[j]);
    }
    if (tid < 64) wlsh[tid] = __ldg(&Wlin[tid]);
    // ---- stage hG = hid0 (padded rows), Lsh = last ----
    {
        const float4* hid04 = reinterpret_cast<const float4*>(hid0);
        for (int i = tid; i < BPC * 16; i += THREADS) {
            int b = i >> 4, c = i & 15;
            *reinterpret_cast<float4*>(hGsh + b * HPAD + c * 4) =
                __ldg(&hid04[(cb0 + b) * 16 + c]);
        }
    }
    if (tid < BPC) {
        int gb = cb0 + tid;
        Lsh[tid] = make_float4(__ldg(&last[gb * 3 + 0]),
                               __ldg(&last[gb * 3 + 1]),
                               __ldg(&last[gb * 3 + 2]), 0.0f);
    }

    // ---- Phase A identity: 16-lane group -> one batch, lane -> 4 dims
    const int sub = lane >> 4, lg = lane & 15;
    const int bA  = w * 2 + sub;
    const int gbA = cb0 + bA;
    const float4* Wl4 = reinterpret_cast<const float4*>(Wlin);
    const float4 wlv = __ldg(&Wl4[lg]);
    const float  bl  = __ldg(blin);

    // encoder slice in registers: 12 t x 4 dims
    const float4* enc4 = reinterpret_cast<const float4*>(enc);
    float4 ev[T_IN];
#pragma unroll
    for (int t = 0; t < T_IN; t++)
        ev[t] = __ldg(&enc4[(t * Bz + gbA) * 16 + lg]);

    // ---- Phase B identity: MMA fragment coords
    const int g  = lane >> 2;     // groupID 0..7 (batch rows g, g+8)
    const int t4 = lane & 3;      // threadID-in-group

    __syncthreads();

#pragma unroll 1
    for (int step = 0; step < T_OUT; step++) {
        // ================= Phase A: out(step-1) + attention =================
        float4 hv = *reinterpret_cast<const float4*>(hGsh + bA * HPAD + lg * 4);

        if (step > 0) {
            float o = dot4(hv, wlv);
            o += __shfl_xor_sync(FULLMASK, o, 8);
            o += __shfl_xor_sync(FULLMASK, o, 4);
            o += __shfl_xor_sync(FULLMASK, o, 2);
            o += __shfl_xor_sync(FULLMASK, o, 1);
            o += bl;
            if (lg == 0) {
                float4 L = Lsh[bA];
                out[gbA * T_OUT + step - 1] = o;
                Lsh[bA] = make_float4(o, L.x, L.y, 0.0f);
            }
        }

        float p[T_IN];
#pragma unroll
        for (int t = 0; t < T_IN; t++)
            p[t] = dot4(ev[t], hv);
#pragma unroll
        for (int off = 8; off > 0; off >>= 1)
#pragma unroll
            for (int t = 0; t < T_IN; t++)
                p[t] += __shfl_xor_sync(FULLMASK, p[t], off);

        // tree-form max and sum
        float m;
        {
            float m0 = fmaxf(p[0], p[1]),  m1 = fmaxf(p[2], p[3]);
            float m2 = fmaxf(p[4], p[5]),  m3 = fmaxf(p[6], p[7]);
            float m4 = fmaxf(p[8], p[9]),  m5 = fmaxf(p[10], p[11]);
            float ma = fmaxf(m0, m1), mb = fmaxf(m2, m3), mc = fmaxf(m4, m5);
            m = fmaxf(fmaxf(ma, mb), mc);
        }
#pragma unroll
        for (int t = 0; t < T_IN; t++) p[t] = __expf(p[t] - m);
        float s;
        {
            float s0 = p[0] + p[1],  s1 = p[2] + p[3];
            float s2 = p[4] + p[5],  s3 = p[6] + p[7];
            float s4 = p[8] + p[9],  s5 = p[10] + p[11];
            float sa = s0 + s1, sb = s2 + s3, sc = s4 + s5;
            s = (sa + sb) + sc;
        }
        float inv = __fdividef(1.0f, s);

        float4 c = make_float4(0.f, 0.f, 0.f, 0.f);
#pragma unroll
        for (int t = 0; t < T_IN; t++) {
            c.x = fmaf(p[t], ev[t].x, c.x); c.y = fmaf(p[t], ev[t].y, c.y);
            c.z = fmaf(p[t], ev[t].z, c.z); c.w = fmaf(p[t], ev[t].w, c.w);
        }
        hv.x = fmaf(c.x, inv, hv.x); hv.y = fmaf(c.y, inv, hv.y);
        hv.z = fmaf(c.z, inv, hv.z); hv.w = fmaf(c.w, inv, hv.w);

        *reinterpret_cast<float4*>(hAsh + bA * HPAD + lg * 4) = hv;

        // ---- prefetch kt=0 B-fragments (step-invariant) BEFORE the barrier
        uint2 bv0[3];
#pragma unroll
        for (int gate = 0; gate < 3; gate++)
            bv0[gate] = Wfr[(((w + 8 * gate)) * 8 + 0) * 32 + lane];

        __syncthreads();

        // ---- gate inputs: issue loads early (in flight under MMA)
        float4 Lg0 = Lsh[g];
        float4 Lg8 = Lsh[g + 8];

        // ============ Phase B: gh = hA @ W_hh^T via tf32 MMA ============
        // warp w computes dims 8w..8w+7 for gates r,z,n over all 16 batches.
        float acc[3][4];
#pragma unroll
        for (int gate = 0; gate < 3; gate++)
#pragma unroll
            for (int ci = 0; ci < 4; ci++) acc[gate][ci] = 0.0f;

#pragma unroll
        for (int kt = 0; kt < 8; kt++) {
            unsigned a0 = cvt_tf32(hAsh[g * HPAD + kt * 8 + t4]);
            unsigned a1 = cvt_tf32(hAsh[(g + 8) * HPAD + kt * 8 + t4]);
            unsigned a2 = cvt_tf32(hAsh[g * HPAD + kt * 8 + t4 + 4]);
            unsigned a3 = cvt_tf32(hAsh[(g + 8) * HPAD + kt * 8 + t4 + 4]);
#pragma unroll
            for (int gate = 0; gate < 3; gate++) {
                uint2 bv = (kt == 0) ? bv0[gate]
                                     : Wfr[((w + 8 * gate) * 8 + kt) * 32 + lane];
                mma_tf32(acc[gate][0], acc[gate][1], acc[gate][2], acc[gate][3],
                         a0, a1, a2, a3, bv.x, bv.y);
            }
        }

        // ---- gates: lane covers batches {g, g+8} x dims {8w+2t4, 8w+2t4+1}
#pragma unroll
        for (int d01 = 0; d01 < 2; d01++) {
            int dim = w * 8 + 2 * t4 + d01;
            float4 gpr = gpsh[dim];
            float4 gpz = gpsh[64 + dim];
            float4 gpn = gpsh[128 + dim];
            float bhr = bhsh[dim], bhz = bhsh[64 + dim], bhn = bhsh[128 + dim];
#pragma unroll
            for (int bb = 0; bb < 2; bb++) {
                int bat = g + 8 * bb;
                float4 L = bb ? Lg8 : Lg0;
                int ci = bb * 2 + d01;
                float ghr = acc[0][ci] + bhr;
                float ghz = acc[1][ci] + bhz;
                float ghn = acc[2][ci] + bhn;
                float gir = fmaf(gpr.x, L.x, fmaf(gpr.y, L.y, fmaf(gpr.z, L.z, gpr.w)));
                float giz = fmaf(gpz.x, L.x, fmaf(gpz.y, L.y, fmaf(gpz.z, L.z, gpz.w)));
                float gin = fmaf(gpn.x, L.x, fmaf(gpn.y, L.y, fmaf(gpn.z, L.z, gpn.w)));
                float r = sigf(gir + ghr);
                float z = sigf(giz + ghz);
                float n = tanhfast(fmaf(r, ghn, gin));
                float hprev = hAsh[bat * HPAD + dim];
                hGsh[bat * HPAD + dim] = fmaf(z, hprev - n, n);
            }
        }
        __syncthreads();
    }

    // ---- final output (step T_OUT-1) from hG ----
    {
        float4 hv = *reinterpret_cast<const float4*>(hGsh + bA * HPAD + lg * 4);
        float o = dot4(hv, wlv);
        o += __shfl_xor_sync(FULLMASK, o, 8);
        o += __shfl_xor_sync(FULLMASK, o, 4);
        o += __shfl_xor_sync(FULLMASK, o, 2);
        o += __shfl_xor_sync(FULLMASK, o, 1);
        o += bl;
        if (lg == 0) out[gbA * T_OUT + T_OUT - 1] = o;
    }
}

extern "C" void kernel_launch(void* const* d_in, const int* in_sizes, int n_in,
                              void* d_out, int out_size) {
    const float* enc  = (const float*)d_in[0];
    const float* hid0 = (const float*)d_in[1];
    const float* last = (const float*)d_in[2];
    const float* Wih  = (const float*)d_in[3];
    const float* Whh  = (const float*)d_in[4];
    const float* bih  = (const float*)d_in[5];
    const float* bhh  = (const float*)d_in[6];
    const float* Wlin = (const float*)d_in[7];
    const float* blin = (const float*)d_in[8];
    float* out = (float*)d_out;

    cudaFuncSetAttribute(decoder_kernel,
                         cudaFuncAttributeMaxDynamicSharedMemorySize,
                         SMEM_BYTES);

    dim3 grid(Bz / BPC);   // 4096 CTAs of 256 threads
    decoder_kernel<<<grid, THREADS, SMEM_BYTES>>>(
        enc, hid0, last, Wih, Whh, bih, bhh, Wlin, blin, out);
}

// round 14
// speedup vs baseline: 1.1379x; 1.1379x over previous
#include <cuda_runtime.h>
#include <cuda_fp16.h>

// Decoder: T_IN=12, B=65536, H=64, T_OUT=12, OVERLAP=3
// 256 threads / 16 batches per CTA, 2 CTAs/SM (4 warps/SMSP).
//   Phase A: 16-lane group owns one batch (2 batches/warp), lane owns 4 dims.
//            Writes fp32 hA (for gate hprev) + packed half2 A-fragment buffer.
//   Phase B: fp16 mma.sync.m16n8k16.f32 — M=16 batches; warp w owns dims
//            8w..8w+7 for gates r,z,n (12 MMAs/warp-step).
// fp16 mantissa (11 bits) == tf32 mantissa -> precision parity with tf32 path.

#define FULLMASK 0xFFFFFFFFu

constexpr int T_IN  = 12;
constexpr int T_OUT = 12;
constexpr int Bz    = 65536;
constexpr int WARPS = 8;
constexpr int THREADS = WARPS * 32;
constexpr int BPC   = 16;            // batches per CTA
constexpr int HPAD  = 68;            // fp32 h row pitch (floats)
constexpr int APH   = 20;            // half2-A buffer pitch per batch (uint2 units)

// SMEM float offsets
constexpr int WFR_U2   = 24 * 4 * 32;           // ntg x ktp x lane (uint2) = 3072
constexpr int OFF_ATF  = WFR_U2 * 2;            // 6144 floats
constexpr int OFF_HA   = OFF_ATF + BPC * APH * 2;   // +640 -> 6784
constexpr int OFF_HG   = OFF_HA + BPC * HPAD;   // +1088 -> 7872
constexpr int OFF_L    = OFF_HG + BPC * HPAD;   // +1088 -> 8960
constexpr int OFF_GP   = OFF_L + BPC * 4;       // 9024
constexpr int OFF_BH   = OFF_GP + 192 * 4;      // 9792
constexpr int OFF_WL   = OFF_BH + 192;          // 9984
constexpr int SMEM_FLOATS = OFF_WL + 64;        // 10048
constexpr int SMEM_BYTES  = SMEM_FLOATS * 4;    // 40,192 B

__device__ __forceinline__ unsigned packh2(float lo, float hi) {
    __half2 h = __floats2half2_rn(lo, hi);
    return *reinterpret_cast<unsigned*>(&h);
}
__device__ __forceinline__ void mma_f16(float& d0, float& d1, float& d2, float& d3,
                                        unsigned a0, unsigned a1, unsigned a2, unsigned a3,
                                        unsigned b0, unsigned b1) {
    asm("mma.sync.aligned.m16n8k16.row.col.f32.f16.f16.f32 "
        "{%0,%1,%2,%3}, {%4,%5,%6,%7}, {%8,%9}, {%0,%1,%2,%3};"
        : "+f"(d0), "+f"(d1), "+f"(d2), "+f"(d3)
        : "r"(a0), "r"(a1), "r"(a2), "r"(a3), "r"(b0), "r"(b1));
}
__device__ __forceinline__ float sigf(float x) {
    return __fdividef(1.0f, 1.0f + __expf(-x));
}
__device__ __forceinline__ float tanhfast(float x) {
    return __fdividef(2.0f, 1.0f + __expf(-2.0f * x)) - 1.0f;
}
__device__ __forceinline__ float dot4(float4 a, float4 b) {
    float s = a.x * b.x;
    s = fmaf(a.y, b.y, s); s = fmaf(a.z, b.z, s); s = fmaf(a.w, b.w, s);
    return s;
}

__global__ void __launch_bounds__(THREADS, 2)
decoder_kernel(const float* __restrict__ enc,    // (12, B, 64)
               const float* __restrict__ hid0,   // (B, 64)
               const float* __restrict__ last,   // (B, 3)
               const float* __restrict__ Wih,    // (192, 3)
               const float* __restrict__ Whh,    // (192, 64)
               const float* __restrict__ bih,    // (192)
               const float* __restrict__ bhh,    // (192)
               const float* __restrict__ Wlin,   // (1, 64)
               const float* __restrict__ blin,   // (1)
               float* __restrict__ out)          // (B, 12)
{
    extern __shared__ float smem[];
    uint2*    Wfr  = reinterpret_cast<uint2*>(smem);
    uint2*    atfh = reinterpret_cast<uint2*>(smem + OFF_ATF);
    unsigned* atfw = reinterpret_cast<unsigned*>(smem + OFF_ATF);
    float*  hAsh = smem + OFF_HA;
    float*  hGsh = smem + OFF_HG;
    float4* Lsh  = reinterpret_cast<float4*>(smem + OFF_L);
    float4* gpsh = reinterpret_cast<float4*>(smem + OFF_GP);   // {wih0,1,2,bih}
    float*  bhsh = smem + OFF_BH;
    float*  wlsh = smem + OFF_WL;

    const int tid  = threadIdx.x;
    const int lane = tid & 31;
    const int w    = tid >> 5;
    const int cb0  = blockIdx.x * BPC;

    // ---- stage W_hh into fp16 B-fragment layout (m16n8k16), once ----
    // Wfr[(ntg*4 + ktp)*32 + ln] = {half2(W[j][16ktp+2t4], W[j][+1]),
    //                               half2(W[j][16ktp+2t4+8], W[j][+9])}
    // ntg = w' + 8*gate; j = gate*64 + w'*8 + (ln>>2); t4 = ln&3
    for (int i = tid; i < WFR_U2; i += THREADS) {
        int ntg = i >> 7;
        int ktp = (i >> 5) & 3;
        int ln  = i & 31;
        int gg  = ln >> 2, t4 = ln & 3;
        int j   = ((ntg >> 3) << 6) + ((ntg & 7) << 3) + gg;
        int k0  = ktp * 16 + 2 * t4;
        Wfr[i] = make_uint2(
            packh2(__ldg(&Whh[j * 64 + k0]),     __ldg(&Whh[j * 64 + k0 + 1])),
            packh2(__ldg(&Whh[j * 64 + k0 + 8]), __ldg(&Whh[j * 64 + k0 + 9])));
    }
    // ---- stage params ----
    for (int j = tid; j < 192; j += THREADS) {
        gpsh[j] = make_float4(__ldg(&Wih[j * 3 + 0]), __ldg(&Wih[j * 3 + 1]),
                              __ldg(&Wih[j * 3 + 2]), __ldg(&bih[j]));
        bhsh[j] = __ldg(&bhh[j]);
    }
    if (tid < 64) wlsh[tid] = __ldg(&Wlin[tid]);
    // ---- stage hG = hid0 (padded rows), Lsh = last ----
    {
        const float4* hid04 = reinterpret_cast<const float4*>(hid0);
        for (int i = tid; i < BPC * 16; i += THREADS) {
            int b = i >> 4, c = i & 15;
            *reinterpret_cast<float4*>(hGsh + b * HPAD + c * 4) =
                __ldg(&hid04[(cb0 + b) * 16 + c]);
        }
    }
    if (tid < BPC) {
        int gb = cb0 + tid;
        Lsh[tid] = make_float4(__ldg(&last[gb * 3 + 0]),
                               __ldg(&last[gb * 3 + 1]),
                               __ldg(&last[gb * 3 + 2]), 0.0f);
    }

    // ---- Phase A identity: 16-lane group -> one batch, lane -> 4 dims
    const int sub = lane >> 4, lg = lane & 15;
    const int bA  = w * 2 + sub;
    const int gbA = cb0 + bA;
    const float4* Wl4 = reinterpret_cast<const float4*>(Wlin);
    const float4 wlv = __ldg(&Wl4[lg]);
    const float  bl  = __ldg(blin);

    // A-buffer store addresses for this lane's 4 dims (dims 4lg..4lg+3):
    // kt = lg>>2; q = lg&3; off = 4q = 2*t4a + 8*field
    const int qA   = lg & 3;
    const int ktA  = lg >> 2;
    const int t4a  = (2 * qA) & 3;
    const int fld  = qA >> 1;
    const int wrd0 = bA * (APH * 2) + ktA * 8 + t4a * 2 + fld;
    const int wrd1 = wrd0 + 2;   // (t4a+1)*2 same field

    // encoder slice in registers: 12 t x 4 dims
    const float4* enc4 = reinterpret_cast<const float4*>(enc);
    float4 ev[T_IN];
#pragma unroll
    for (int t = 0; t < T_IN; t++)
        ev[t] = __ldg(&enc4[(t * Bz + gbA) * 16 + lg]);

    // ---- Phase B identity: MMA fragment coords
    const int g  = lane >> 2;     // groupID 0..7 (batch rows g, g+8)
    const int t4 = lane & 3;      // threadID-in-group

    __syncthreads();

#pragma unroll 1
    for (int step = 0; step < T_OUT; step++) {
        // ================= Phase A: out(step-1) + attention =================
        float4 hv = *reinterpret_cast<const float4*>(hGsh + bA * HPAD + lg * 4);

        if (step > 0) {
            float o = dot4(hv, wlv);
            o += __shfl_xor_sync(FULLMASK, o, 8);
            o += __shfl_xor_sync(FULLMASK, o, 4);
            o += __shfl_xor_sync(FULLMASK, o, 2);
            o += __shfl_xor_sync(FULLMASK, o, 1);
            o += bl;
            if (lg == 0) {
                float4 L = Lsh[bA];
                out[gbA * T_OUT + step - 1] = o;
                Lsh[bA] = make_float4(o, L.x, L.y, 0.0f);
            }
        }

        float p[T_IN];
#pragma unroll
        for (int t = 0; t < T_IN; t++)
            p[t] = dot4(ev[t], hv);
#pragma unroll
        for (int off = 8; off > 0; off >>= 1)
#pragma unroll
            for (int t = 0; t < T_IN; t++)
                p[t] += __shfl_xor_sync(FULLMASK, p[t], off);

        // tree-form max and sum
        float m;
        {
            float m0 = fmaxf(p[0], p[1]),  m1 = fmaxf(p[2], p[3]);
            float m2 = fmaxf(p[4], p[5]),  m3 = fmaxf(p[6], p[7]);
            float m4 = fmaxf(p[8], p[9]),  m5 = fmaxf(p[10], p[11]);
            float ma = fmaxf(m0, m1), mb = fmaxf(m2, m3), mc = fmaxf(m4, m5);
            m = fmaxf(fmaxf(ma, mb), mc);
        }
#pragma unroll
        for (int t = 0; t < T_IN; t++) p[t] = __expf(p[t] - m);
        float s;
        {
            float s0 = p[0] + p[1],  s1 = p[2] + p[3];
            float s2 = p[4] + p[5],  s3 = p[6] + p[7];
            float s4 = p[8] + p[9],  s5 = p[10] + p[11];
            float sa = s0 + s1, sb = s2 + s3, sc = s4 + s5;
            s = (sa + sb) + sc;
        }
        float inv = __fdividef(1.0f, s);

        float4 c = make_float4(0.f, 0.f, 0.f, 0.f);
#pragma unroll
        for (int t = 0; t < T_IN; t++) {
            c.x = fmaf(p[t], ev[t].x, c.x); c.y = fmaf(p[t], ev[t].y, c.y);
            c.z = fmaf(p[t], ev[t].z, c.z); c.w = fmaf(p[t], ev[t].w, c.w);
        }
        hv.x = fmaf(c.x, inv, hv.x); hv.y = fmaf(c.y, inv, hv.y);
        hv.z = fmaf(c.z, inv, hv.z); hv.w = fmaf(c.w, inv, hv.w);

        // fp32 hA (for hprev in gates)
        *reinterpret_cast<float4*>(hAsh + bA * HPAD + lg * 4) = hv;
        // half2 A-fragment copy (pairs (d,d+1) of this lane's 4 dims)
        atfw[wrd0] = packh2(hv.x, hv.y);
        atfw[wrd1] = packh2(hv.z, hv.w);

        // ---- prefetch ktp=0 B-fragments (step-invariant) BEFORE the barrier
        uint2 bv0[3];
#pragma unroll
        for (int gate = 0; gate < 3; gate++)
            bv0[gate] = Wfr[((w + 8 * gate) * 4 + 0) * 32 + lane];

        __syncthreads();

        // ---- gate inputs: issue loads early (in flight under MMA)
        float4 Lg0 = Lsh[g];
        float4 Lg8 = Lsh[g + 8];

        // ============ Phase B: gh = hA @ W_hh^T via fp16 MMA ============
        // warp w computes dims 8w..8w+7 for gates r,z,n over all 16 batches.
        float acc[3][4];
#pragma unroll
        for (int gate = 0; gate < 3; gate++)
#pragma unroll
            for (int ci = 0; ci < 4; ci++) acc[gate][ci] = 0.0f;

#pragma unroll
        for (int ktp = 0; ktp < 4; ktp++) {
            uint2 Ag0 = atfh[g * APH + ktp * 4 + t4];
            uint2 Ag8 = atfh[(g + 8) * APH + ktp * 4 + t4];
#pragma unroll
            for (int gate = 0; gate < 3; gate++) {
                uint2 bv = (ktp == 0) ? bv0[gate]
                                      : Wfr[((w + 8 * gate) * 4 + ktp) * 32 + lane];
                mma_f16(acc[gate][0], acc[gate][1], acc[gate][2], acc[gate][3],
                        Ag0.x, Ag8.x, Ag0.y, Ag8.y, bv.x, bv.y);
            }
        }

        // ---- gates: lane covers batches {g, g+8} x dims {8w+2t4, 8w+2t4+1}
#pragma unroll
        for (int d01 = 0; d01 < 2; d01++) {
            int dim = w * 8 + 2 * t4 + d01;
            float4 gpr = gpsh[dim];
            float4 gpz = gpsh[64 + dim];
            float4 gpn = gpsh[128 + dim];
            float bhr = bhsh[dim], bhz = bhsh[64 + dim], bhn = bhsh[128 + dim];
#pragma unroll
            for (int bb = 0; bb < 2; bb++) {
                int bat = g + 8 * bb;
                float4 L = bb ? Lg8 : Lg0;
                int ci = bb * 2 + d01;
                float ghr = acc[0][ci] + bhr;
                float ghz = acc[1][ci] + bhz;
                float ghn = acc[2][ci] + bhn;
                float gir = fmaf(gpr.x, L.x, fmaf(gpr.y, L.y, fmaf(gpr.z, L.z, gpr.w)));
                float giz = fmaf(gpz.x, L.x, fmaf(gpz.y, L.y, fmaf(gpz.z, L.z, gpz.w)));
                float gin = fmaf(gpn.x, L.x, fmaf(gpn.y, L.y, fmaf(gpn.z, L.z, gpn.w)));
                float r = sigf(gir + ghr);
                float z = sigf(giz + ghz);
                float n = tanhfast(fmaf(r, ghn, gin));
                float hprev = hAsh[bat * HPAD + dim];
                hGsh[bat * HPAD + dim] = fmaf(z, hprev - n, n);
            }
        }
        __syncthreads();
    }

    // ---- final output (step T_OUT-1) from hG ----
    {
        float4 hv = *reinterpret_cast<const float4*>(hGsh + bA * HPAD + lg * 4);
        float o = dot4(hv, wlv);
        o += __shfl_xor_sync(FULLMASK, o, 8);
        o += __shfl_xor_sync(FULLMASK, o, 4);
        o += __shfl_xor_sync(FULLMASK, o, 2);
        o += __shfl_xor_sync(FULLMASK, o, 1);
        o += bl;
        if (lg == 0) out[gbA * T_OUT + T_OUT - 1] = o;
    }
}

extern "C" void kernel_launch(void* const* d_in, const int* in_sizes, int n_in,
                              void* d_out, int out_size) {
    const float* enc  = (const float*)d_in[0];
    const float* hid0 = (const float*)d_in[1];
    const float* last = (const float*)d_in[2];
    const float* Wih  = (const float*)d_in[3];
    const float* Whh  = (const float*)d_in[4];
    const float* bih  = (const float*)d_in[5];
    const float* bhh  = (const float*)d_in[6];
    const float* Wlin = (const float*)d_in[7];
    const float* blin = (const float*)d_in[8];
    float* out = (float*)d_out;

    cudaFuncSetAttribute(decoder_kernel,
                         cudaFuncAttributeMaxDynamicSharedMemorySize,
                         SMEM_BYTES);

    dim3 grid(Bz / BPC);   // 4096 CTAs of 256 threads
    decoder_kernel<<<grid, THREADS, SMEM_BYTES>>>(
        enc, hid0, last, Wih, Whh, bih, bhh, Wlin, blin, out);
}

// round 15
// speedup vs baseline: 1.2211x; 1.0731x over previous
#include <cuda_runtime.h>
#include <cuda_fp16.h>

// Decoder: T_IN=12, B=65536, H=64, T_OUT=12, OVERLAP=3
// 256 threads / 16 batches per CTA, 2 CTAs/SM (4 warps/SMSP).
//   Phase A (t-split): lane = 8*th + dl within a 16-lane batch group;
//     lane owns dims [8dl,8dl+8) x timesteps [6th,6th+6).
//     Logit reduce: 3-round butterfly over dl (18 SHFL) + cross-half (off 8).
//   Phase B: fp16 mma.sync.m16n8k16.f32 — warp w owns dims 8w..8w+7 for
//     gates r,z,n. A-fragments in two bank-perfect word arrays (pitch 36).
// gh MMA inputs/order identical to R13 (bit-identical matvec numerics).

#define FULLMASK 0xFFFFFFFFu

constexpr int T_IN  = 12;
constexpr int T_OUT = 12;
constexpr int Bz    = 65536;
constexpr int WARPS = 8;
constexpr int THREADS = WARPS * 32;
constexpr int BPC   = 16;            // batches per CTA
constexpr int HPAD  = 68;            // fp32 h row pitch (floats)
constexpr int APW   = 36;            // A-array per-batch pitch in 32-bit words

// SMEM float(=word) offsets
constexpr int WFR_U2    = 24 * 4 * 32;          // ntg x ktp x lane (uint2) = 3072
constexpr int OFF_ATF0  = WFR_U2 * 2;           // 6144
constexpr int OFF_ATF1  = OFF_ATF0 + BPC * APW; // 6720
constexpr int OFF_HA    = OFF_ATF1 + BPC * APW; // 7296
constexpr int OFF_HG    = OFF_HA + BPC * HPAD;  // 8384
constexpr int OFF_L     = OFF_HG + BPC * HPAD;  // 9472
constexpr int OFF_GP    = OFF_L + BPC * 4;      // 9536
constexpr int OFF_BH    = OFF_GP + 192 * 4;     // 10304
constexpr int OFF_WL    = OFF_BH + 192;         // 10496
constexpr int SMEM_FLOATS = OFF_WL + 64;        // 10560
constexpr int SMEM_BYTES  = SMEM_FLOATS * 4;    // 42,240 B

__device__ __forceinline__ unsigned packh2(float lo, float hi) {
    __half2 h = __floats2half2_rn(lo, hi);
    return *reinterpret_cast<unsigned*>(&h);
}
__device__ __forceinline__ void mma_f16(float& d0, float& d1, float& d2, float& d3,
                                        unsigned a0, unsigned a1, unsigned a2, unsigned a3,
                                        unsigned b0, unsigned b1) {
    asm("mma.sync.aligned.m16n8k16.row.col.f32.f16.f16.f32 "
        "{%0,%1,%2,%3}, {%4,%5,%6,%7}, {%8,%9}, {%0,%1,%2,%3};"
        : "+f"(d0), "+f"(d1), "+f"(d2), "+f"(d3)
        : "r"(a0), "r"(a1), "r"(a2), "r"(a3), "r"(b0), "r"(b1));
}
__device__ __forceinline__ float sigf(float x) {
    return __fdividef(1.0f, 1.0f + __expf(-x));
}
__device__ __forceinline__ float tanhfast(float x) {
    return __fdividef(2.0f, 1.0f + __expf(-2.0f * x)) - 1.0f;
}
__device__ __forceinline__ float dot8(float4 a, float4 b, float4 c, float4 d) {
    float s = a.x * b.x;
    s = fmaf(a.y, b.y, s); s = fmaf(a.z, b.z, s); s = fmaf(a.w, b.w, s);
    s = fmaf(c.x, d.x, s); s = fmaf(c.y, d.y, s);
    s = fmaf(c.z, d.z, s); s = fmaf(c.w, d.w, s);
    return s;
}

__global__ void __launch_bounds__(THREADS, 2)
decoder_kernel(const float* __restrict__ enc,    // (12, B, 64)
               const float* __restrict__ hid0,   // (B, 64)
               const float* __restrict__ last,   // (B, 3)
               const float* __restrict__ Wih,    // (192, 3)
               const float* __restrict__ Whh,    // (192, 64)
               const float* __restrict__ bih,    // (192)
               const float* __restrict__ bhh,    // (192)
               const float* __restrict__ Wlin,   // (1, 64)
               const float* __restrict__ blin,   // (1)
               float* __restrict__ out)          // (B, 12)
{
    extern __shared__ float smem[];
    uint2*    Wfr   = reinterpret_cast<uint2*>(smem);
    unsigned* atf0w = reinterpret_cast<unsigned*>(smem + OFF_ATF0);
    unsigned* atf1w = reinterpret_cast<unsigned*>(smem + OFF_ATF1);
    float*  hAsh = smem + OFF_HA;
    float*  hGsh = smem + OFF_HG;
    float4* Lsh  = reinterpret_cast<float4*>(smem + OFF_L);
    float4* gpsh = reinterpret_cast<float4*>(smem + OFF_GP);   // {wih0,1,2,bih}
    float*  bhsh = smem + OFF_BH;
    float*  wlsh = smem + OFF_WL;

    const int tid  = threadIdx.x;
    const int lane = tid & 31;
    const int w    = tid >> 5;
    const int cb0  = blockIdx.x * BPC;

    // ---- stage W_hh into fp16 B-fragment layout (m16n8k16), once ----
    for (int i = tid; i < WFR_U2; i += THREADS) {
        int ntg = i >> 7;
        int ktp = (i >> 5) & 3;
        int ln  = i & 31;
        int gg  = ln >> 2, t4 = ln & 3;
        int j   = ((ntg >> 3) << 6) + ((ntg & 7) << 3) + gg;
        int k0  = ktp * 16 + 2 * t4;
        Wfr[i] = make_uint2(
            packh2(__ldg(&Whh[j * 64 + k0]),     __ldg(&Whh[j * 64 + k0 + 1])),
            packh2(__ldg(&Whh[j * 64 + k0 + 8]), __ldg(&Whh[j * 64 + k0 + 9])));
    }
    // ---- stage params ----
    for (int j = tid; j < 192; j += THREADS) {
        gpsh[j] = make_float4(__ldg(&Wih[j * 3 + 0]), __ldg(&Wih[j * 3 + 1]),
                              __ldg(&Wih[j * 3 + 2]), __ldg(&bih[j]));
        bhsh[j] = __ldg(&bhh[j]);
    }
    if (tid < 64) wlsh[tid] = __ldg(&Wlin[tid]);
    // ---- stage hG = hid0 (padded rows), Lsh = last ----
    {
        const float4* hid04 = reinterpret_cast<const float4*>(hid0);
        for (int i = tid; i < BPC * 16; i += THREADS) {
            int b = i >> 4, c = i & 15;
            *reinterpret_cast<float4*>(hGsh + b * HPAD + c * 4) =
                __ldg(&hid04[(cb0 + b) * 16 + c]);
        }
    }
    if (tid < BPC) {
        int gb = cb0 + tid;
        Lsh[tid] = make_float4(__ldg(&last[gb * 3 + 0]),
                               __ldg(&last[gb * 3 + 1]),
                               __ldg(&last[gb * 3 + 2]), 0.0f);
    }

    // ---- Phase A identity: lane = 16*sub + 8*th + dl
    const int sub = lane >> 4;
    const int l16 = lane & 15;
    const int th  = l16 >> 3;       // timestep half: t = 6*th .. 6*th+5
    const int dl  = l16 & 7;        // dim lane: dims 8*dl .. 8*dl+7
    const int bA  = w * 2 + sub;
    const int gbA = cb0 + bA;
    const float4* Wl4 = reinterpret_cast<const float4*>(Wlin);
    const float4 wl0 = __ldg(&Wl4[dl * 2]);
    const float4 wl1 = __ldg(&Wl4[dl * 2 + 1]);
    const float  bl  = __ldg(blin);

    // atf store target (th==0 lanes only): array (dl&1), word base
    unsigned* atfdst = ((dl & 1) ? atf1w : atf0w) + bA * APW + (dl >> 1) * 4;

    // encoder slice: 6 timesteps x 8 dims
    const float4* enc4 = reinterpret_cast<const float4*>(enc);
    float4 ev0[6], ev1[6];
#pragma unroll
    for (int j = 0; j < 6; j++) {
        int t = 6 * th + j;
        int idx = (t * Bz + gbA) * 16 + dl * 2;
        ev0[j] = __ldg(&enc4[idx]);
        ev1[j] = __ldg(&enc4[idx + 1]);
    }

    // ---- Phase B identity: MMA fragment coords
    const int g  = lane >> 2;     // groupID 0..7 (batch rows g, g+8)
    const int t4 = lane & 3;      // threadID-in-group

    __syncthreads();

#pragma unroll 1
    for (int step = 0; step < T_OUT; step++) {
        // ================= Phase A: out(step-1) + attention =================
        float4 h0 = *reinterpret_cast<const float4*>(hGsh + bA * HPAD + dl * 8);
        float4 h1 = *reinterpret_cast<const float4*>(hGsh + bA * HPAD + dl * 8 + 4);

        if (step > 0) {
            float o = dot8(h0, wl0, h1, wl1);
            o += __shfl_xor_sync(FULLMASK, o, 4);
            o += __shfl_xor_sync(FULLMASK, o, 2);
            o += __shfl_xor_sync(FULLMASK, o, 1);
            o += bl;
            if (l16 == 0) {
                float4 L = Lsh[bA];
                out[gbA * T_OUT + step - 1] = o;
                Lsh[bA] = make_float4(o, L.x, L.y, 0.0f);
            }
        }

        // logits for this half's 6 timesteps (partial over 8 dims -> full)
        float p[6];
#pragma unroll
        for (int j = 0; j < 6; j++)
            p[j] = dot8(ev0[j], h0, ev1[j], h1);
#pragma unroll
        for (int off = 4; off > 0; off >>= 1)
#pragma unroll
            for (int j = 0; j < 6; j++)
                p[j] += __shfl_xor_sync(FULLMASK, p[j], off);

        // global max over 12 logits (local 6 + cross-half)
        float m6 = fmaxf(fmaxf(fmaxf(p[0], p[1]), fmaxf(p[2], p[3])),
                         fmaxf(p[4], p[5]));
        float mo = __shfl_xor_sync(FULLMASK, m6, 8);
        float m  = fmaxf(m6, mo);

#pragma unroll
        for (int j = 0; j < 6; j++) p[j] = __expf(p[j] - m);
        float s6 = ((p[0] + p[1]) + (p[2] + p[3])) + (p[4] + p[5]);
        float so = __shfl_xor_sync(FULLMASK, s6, 8);
        // th-symmetric order: both halves compute sum(t0-5) + sum(t6-11)
        float sA = th ? so : s6;
        float sB = th ? s6 : so;
        float inv = __fdividef(1.0f, sA + sB);

        // context partial over this half's 6 timesteps
        float4 c0 = make_float4(0.f, 0.f, 0.f, 0.f);
        float4 c1 = make_float4(0.f, 0.f, 0.f, 0.f);
#pragma unroll
        for (int j = 0; j < 6; j++) {
            c0.x = fmaf(p[j], ev0[j].x, c0.x); c0.y = fmaf(p[j], ev0[j].y, c0.y);
            c0.z = fmaf(p[j], ev0[j].z, c0.z); c0.w = fmaf(p[j], ev0[j].w, c0.w);
            c1.x = fmaf(p[j], ev1[j].x, c1.x); c1.y = fmaf(p[j], ev1[j].y, c1.y);
            c1.z = fmaf(p[j], ev1[j].z, c1.z); c1.w = fmaf(p[j], ev1[j].w, c1.w);
        }
        // cross-half combine (full sum over 12 timesteps)
        c0.x += __shfl_xor_sync(FULLMASK, c0.x, 8);
        c0.y += __shfl_xor_sync(FULLMASK, c0.y, 8);
        c0.z += __shfl_xor_sync(FULLMASK, c0.z, 8);
        c0.w += __shfl_xor_sync(FULLMASK, c0.w, 8);
        c1.x += __shfl_xor_sync(FULLMASK, c1.x, 8);
        c1.y += __shfl_xor_sync(FULLMASK, c1.y, 8);
        c1.z += __shfl_xor_sync(FULLMASK, c1.z, 8);
        c1.w += __shfl_xor_sync(FULLMASK, c1.w, 8);

        h0.x = fmaf(c0.x, inv, h0.x); h0.y = fmaf(c0.y, inv, h0.y);
        h0.z = fmaf(c0.z, inv, h0.z); h0.w = fmaf(c0.w, inv, h0.w);
        h1.x = fmaf(c1.x, inv, h1.x); h1.y = fmaf(c1.y, inv, h1.y);
        h1.z = fmaf(c1.z, inv, h1.z); h1.w = fmaf(c1.w, inv, h1.w);

        if (th == 0) {
            // fp32 hA (for hprev in gates)
            *reinterpret_cast<float4*>(hAsh + bA * HPAD + dl * 8)     = h0;
            *reinterpret_cast<float4*>(hAsh + bA * HPAD + dl * 8 + 4) = h1;
            // half2 A-fragment: 4 consecutive words in array (dl&1)
            *reinterpret_cast<uint4*>(atfdst) =
                make_uint4(packh2(h0.x, h0.y), packh2(h0.z, h0.w),
                           packh2(h1.x, h1.y), packh2(h1.z, h1.w));
        }

        // ---- prefetch ktp=0 B-fragments (step-invariant) BEFORE the barrier
        uint2 bv0[3];
#pragma unroll
        for (int gate = 0; gate < 3; gate++)
            bv0[gate] = Wfr[((w + 8 * gate) * 4 + 0) * 32 + lane];

        __syncthreads();

        // ---- gate inputs: issue loads early (in flight under MMA)
        float4 Lg0 = Lsh[g];
        float4 Lg8 = Lsh[g + 8];

        // ============ Phase B: gh = hA @ W_hh^T via fp16 MMA ============
        float acc[3][4];
#pragma unroll
        for (int gate = 0; gate < 3; gate++)
#pragma unroll
            for (int ci = 0; ci < 4; ci++) acc[gate][ci] = 0.0f;

#pragma unroll
        for (int ktp = 0; ktp < 4; ktp++) {
            int wi = ktp * 4 + t4;
            unsigned a0 = atf0w[g * APW + wi];
            unsigned a1 = atf0w[(g + 8) * APW + wi];
            unsigned a2 = atf1w[g * APW + wi];
            unsigned a3 = atf1w[(g + 8) * APW + wi];
#pragma unroll
            for (int gate = 0; gate < 3; gate++) {
                uint2 bv = (ktp == 0) ? bv0[gate]
                                      : Wfr[((w + 8 * gate) * 4 + ktp) * 32 + lane];
                mma_f16(acc[gate][0], acc[gate][1], acc[gate][2], acc[gate][3],
                        a0, a1, a2, a3, bv.x, bv.y);
            }
        }

        // ---- gates: lane covers batches {g, g+8} x dims {8w+2t4, 8w+2t4+1}
#pragma unroll
        for (int d01 = 0; d01 < 2; d01++) {
            int dim = w * 8 + 2 * t4 + d01;
            float4 gpr = gpsh[dim];
            float4 gpz = gpsh[64 + dim];
            float4 gpn = gpsh[128 + dim];
            float bhr = bhsh[dim], bhz = bhsh[64 + dim], bhn = bhsh[128 + dim];
#pragma unroll
            for (int bb = 0; bb < 2; bb++) {
                int bat = g + 8 * bb;
                float4 L = bb ? Lg8 : Lg0;
                int ci = bb * 2 + d01;
                float ghr = acc[0][ci] + bhr;
                float ghz = acc[1][ci] + bhz;
                float ghn = acc[2][ci] + bhn;
                float gir = fmaf(gpr.x, L.x, fmaf(gpr.y, L.y, fmaf(gpr.z, L.z, gpr.w)));
                float giz = fmaf(gpz.x, L.x, fmaf(gpz.y, L.y, fmaf(gpz.z, L.z, gpz.w)));
                float gin = fmaf(gpn.x, L.x, fmaf(gpn.y, L.y, fmaf(gpn.z, L.z, gpn.w)));
                float r = sigf(gir + ghr);
                float z = sigf(giz + ghz);
                float n = tanhfast(fmaf(r, ghn, gin));
                float hprev = hAsh[bat * HPAD + dim];
                hGsh[bat * HPAD + dim] = fmaf(z, hprev - n, n);
            }
        }
        __syncthreads();
    }

    // ---- final output (step T_OUT-1) from hG ----
    {
        float4 h0 = *reinterpret_cast<const float4*>(hGsh + bA * HPAD + dl * 8);
        float4 h1 = *reinterpret_cast<const float4*>(hGsh + bA * HPAD + dl * 8 + 4);
        float o = dot8(h0, wl0, h1, wl1);
        o += __shfl_xor_sync(FULLMASK, o, 4);
        o += __shfl_xor_sync(FULLMASK, o, 2);
        o += __shfl_xor_sync(FULLMASK, o, 1);
        o += bl;
        if (l16 == 0) out[gbA * T_OUT + T_OUT - 1] = o;
    }
}

extern "C" void kernel_launch(void* const* d_in, const int* in_sizes, int n_in,
                              void* d_out, int out_size) {
    const float* enc  = (const float*)d_in[0];
    const float* hid0 = (const float*)d_in[1];
    const float* last = (const float*)d_in[2];
    const float* Wih  = (const float*)d_in[3];
    const float* Whh  = (const float*)d_in[4];
    const float* bih  = (const float*)d_in[5];
    const float* bhh  = (const float*)d_in[6];
    const float* Wlin = (const float*)d_in[7];
    const float* blin = (const float*)d_in[8];
    float* out = (float*)d_out;

    cudaFuncSetAttribute(decoder_kernel,
                         cudaFuncAttributeMaxDynamicSharedMemorySize,
                         SMEM_BYTES);

    dim3 grid(Bz / BPC);   // 4096 CTAs of 256 threads
    decoder_kernel<<<grid, THREADS, SMEM_BYTES>>>(
        enc, hid0, last, Wih, Whh, bih, bhh, Wlin, blin, out);
}

// round 16
// speedup vs baseline: 1.2454x; 1.0199x over previous
#include <cuda_runtime.h>
#include <cuda_fp16.h>

// Decoder: T_IN=12, B=65536, H=64, T_OUT=12, OVERLAP=3
// 256 threads / 16 batches per CTA, 2 CTAs/SM (4 warps/SMSP).
//   Phase A (t-split): lane = 8*th + dl within a 16-lane batch group;
//     lane owns dims [8dl,8dl+8) x timesteps [6th,6th+6).
//   Phase B: fp16 mma.sync.m16n8k16.f32 — warp w owns dims 8w..8w+7 for
//     gates r,z,n. B-fragments (W_hh) are REGISTER-RESIDENT (24 regs/thread,
//     loaded once) — no per-step W smem traffic at all.
// gh MMA inputs/order identical to R13/R14 (bit-identical matvec numerics).

#define FULLMASK 0xFFFFFFFFu

constexpr int T_IN  = 12;
constexpr int T_OUT = 12;
constexpr int Bz    = 65536;
constexpr int WARPS = 8;
constexpr int THREADS = WARPS * 32;
constexpr int BPC   = 16;            // batches per CTA
constexpr int HPAD  = 68;            // fp32 h row pitch (floats)
constexpr int APW   = 36;            // A-array per-batch pitch in 32-bit words

// SMEM word offsets (W_hh no longer staged in smem)
constexpr int OFF_ATF0  = 0;
constexpr int OFF_ATF1  = OFF_ATF0 + BPC * APW;   // 576
constexpr int OFF_HA    = OFF_ATF1 + BPC * APW;   // 1152
constexpr int OFF_HG    = OFF_HA + BPC * HPAD;    // 2240
constexpr int OFF_L     = OFF_HG + BPC * HPAD;    // 3328
constexpr int OFF_GP    = OFF_L + BPC * 4;        // 3392
constexpr int OFF_BH    = OFF_GP + 192 * 4;       // 4160
constexpr int OFF_WL    = OFF_BH + 192;           // 4352
constexpr int SMEM_FLOATS = OFF_WL + 64;          // 4416
constexpr int SMEM_BYTES  = SMEM_FLOATS * 4;      // 17,664 B

__device__ __forceinline__ unsigned packh2(float lo, float hi) {
    __half2 h = __floats2half2_rn(lo, hi);
    return *reinterpret_cast<unsigned*>(&h);
}
__device__ __forceinline__ void mma_f16(float& d0, float& d1, float& d2, float& d3,
                                        unsigned a0, unsigned a1, unsigned a2, unsigned a3,
                                        unsigned b0, unsigned b1) {
    asm("mma.sync.aligned.m16n8k16.row.col.f32.f16.f16.f32 "
        "{%0,%1,%2,%3}, {%4,%5,%6,%7}, {%8,%9}, {%0,%1,%2,%3};"
        : "+f"(d0), "+f"(d1), "+f"(d2), "+f"(d3)
        : "r"(a0), "r"(a1), "r"(a2), "r"(a3), "r"(b0), "r"(b1));
}
__device__ __forceinline__ float sigf(float x) {
    return __fdividef(1.0f, 1.0f + __expf(-x));
}
__device__ __forceinline__ float tanhfast(float x) {
    return __fdividef(2.0f, 1.0f + __expf(-2.0f * x)) - 1.0f;
}
__device__ __forceinline__ float dot8(float4 a, float4 b, float4 c, float4 d) {
    float s = a.x * b.x;
    s = fmaf(a.y, b.y, s); s = fmaf(a.z, b.z, s); s = fmaf(a.w, b.w, s);
    s = fmaf(c.x, d.x, s); s = fmaf(c.y, d.y, s);
    s = fmaf(c.z, d.z, s); s = fmaf(c.w, d.w, s);
    return s;
}

__global__ void __launch_bounds__(THREADS, 2)
decoder_kernel(const float* __restrict__ enc,    // (12, B, 64)
               const float* __restrict__ hid0,   // (B, 64)
               const float* __restrict__ last,   // (B, 3)
               const float* __restrict__ Wih,    // (192, 3)
               const float* __restrict__ Whh,    // (192, 64)
               const float* __restrict__ bih,    // (192)
               const float* __restrict__ bhh,    // (192)
               const float* __restrict__ Wlin,   // (1, 64)
               const float* __restrict__ blin,   // (1)
               float* __restrict__ out)          // (B, 12)
{
    extern __shared__ float smem[];
    unsigned* atf0w = reinterpret_cast<unsigned*>(smem + OFF_ATF0);
    unsigned* atf1w = reinterpret_cast<unsigned*>(smem + OFF_ATF1);
    float*  hAsh = smem + OFF_HA;
    float*  hGsh = smem + OFF_HG;
    float4* Lsh  = reinterpret_cast<float4*>(smem + OFF_L);
    float4* gpsh = reinterpret_cast<float4*>(smem + OFF_GP);   // {wih0,1,2,bih}
    float*  bhsh = smem + OFF_BH;
    float*  wlsh = smem + OFF_WL;

    const int tid  = threadIdx.x;
    const int lane = tid & 31;
    const int w    = tid >> 5;
    const int cb0  = blockIdx.x * BPC;

    // ---- B-fragments of W_hh: REGISTER-RESIDENT, loaded once ----
    // breg[gate][ktp] = {half2(W[j][k0], W[j][k0+1]), half2(W[j][k0+8], W[j][k0+9])}
    // j = gate*64 + w*8 + (lane>>2); k0 = ktp*16 + 2*(lane&3)
    uint2 breg[3][4];
    {
        int j0 = w * 8 + (lane >> 2);
        int c0 = 2 * (lane & 3);
#pragma unroll
        for (int gate = 0; gate < 3; gate++) {
            const float* row = Whh + (gate * 64 + j0) * 64;
#pragma unroll
            for (int ktp = 0; ktp < 4; ktp++) {
                int k0 = ktp * 16 + c0;
                breg[gate][ktp] = make_uint2(
                    packh2(__ldg(&row[k0]),     __ldg(&row[k0 + 1])),
                    packh2(__ldg(&row[k0 + 8]), __ldg(&row[k0 + 9])));
            }
        }
    }
    // ---- stage params ----
    for (int j = tid; j < 192; j += THREADS) {
        gpsh[j] = make_float4(__ldg(&Wih[j * 3 + 0]), __ldg(&Wih[j * 3 + 1]),
                              __ldg(&Wih[j * 3 + 2]), __ldg(&bih[j]));
        bhsh[j] = __ldg(&bhh[j]);
    }
    if (tid < 64) wlsh[tid] = __ldg(&Wlin[tid]);
    // ---- stage hG = hid0 (padded rows), Lsh = last ----
    {
        const float4* hid04 = reinterpret_cast<const float4*>(hid0);
        for (int i = tid; i < BPC * 16; i += THREADS) {
            int b = i >> 4, c = i & 15;
            *reinterpret_cast<float4*>(hGsh + b * HPAD + c * 4) =
                __ldg(&hid04[(cb0 + b) * 16 + c]);
        }
    }
    if (tid < BPC) {
        int gb = cb0 + tid;
        Lsh[tid] = make_float4(__ldg(&last[gb * 3 + 0]),
                               __ldg(&last[gb * 3 + 1]),
                               __ldg(&last[gb * 3 + 2]), 0.0f);
    }

    // ---- Phase A identity: lane = 16*sub + 8*th + dl
    const int sub = lane >> 4;
    const int l16 = lane & 15;
    const int th  = l16 >> 3;       // timestep half: t = 6*th .. 6*th+5
    const int dl  = l16 & 7;        // dim lane: dims 8*dl .. 8*dl+7
    const int bA  = w * 2 + sub;
    const int gbA = cb0 + bA;
    const float bl = __ldg(blin);
    const float4* Wl4s = reinterpret_cast<const float4*>(wlsh);

    // atf store target (th==0 lanes only): array (dl&1), word base
    unsigned* atfdst = ((dl & 1) ? atf1w : atf0w) + bA * APW + (dl >> 1) * 4;

    // encoder slice: 6 timesteps x 8 dims
    const float4* enc4 = reinterpret_cast<const float4*>(enc);
    float4 ev0[6], ev1[6];
#pragma unroll
    for (int j = 0; j < 6; j++) {
        int t = 6 * th + j;
        int idx = (t * Bz + gbA) * 16 + dl * 2;
        ev0[j] = __ldg(&enc4[idx]);
        ev1[j] = __ldg(&enc4[idx + 1]);
    }

    // ---- Phase B identity: MMA fragment coords
    const int g  = lane >> 2;     // groupID 0..7 (batch rows g, g+8)
    const int t4 = lane & 3;      // threadID-in-group

    __syncthreads();

#pragma unroll 1
    for (int step = 0; step < T_OUT; step++) {
        // ================= Phase A: out(step-1) + attention =================
        float4 h0 = *reinterpret_cast<const float4*>(hGsh + bA * HPAD + dl * 8);
        float4 h1 = *reinterpret_cast<const float4*>(hGsh + bA * HPAD + dl * 8 + 4);

        if (step > 0) {
            float4 wl0 = Wl4s[dl * 2];
            float4 wl1 = Wl4s[dl * 2 + 1];
            float o = dot8(h0, wl0, h1, wl1);
            o += __shfl_xor_sync(FULLMASK, o, 4);
            o += __shfl_xor_sync(FULLMASK, o, 2);
            o += __shfl_xor_sync(FULLMASK, o, 1);
            o += bl;
            if (l16 == 0) {
                float4 L = Lsh[bA];
                out[gbA * T_OUT + step - 1] = o;
                Lsh[bA] = make_float4(o, L.x, L.y, 0.0f);
            }
        }

        // logits for this half's 6 timesteps (partial over 8 dims -> full)
        float p[6];
#pragma unroll
        for (int j = 0; j < 6; j++)
            p[j] = dot8(ev0[j], h0, ev1[j], h1);
#pragma unroll
        for (int off = 4; off > 0; off >>= 1)
#pragma unroll
            for (int j = 0; j < 6; j++)
                p[j] += __shfl_xor_sync(FULLMASK, p[j], off);

        // global max over 12 logits (local 6 + cross-half)
        float m6 = fmaxf(fmaxf(fmaxf(p[0], p[1]), fmaxf(p[2], p[3])),
                         fmaxf(p[4], p[5]));
        float mo = __shfl_xor_sync(FULLMASK, m6, 8);
        float m  = fmaxf(m6, mo);

#pragma unroll
        for (int j = 0; j < 6; j++) p[j] = __expf(p[j] - m);
        float s6 = ((p[0] + p[1]) + (p[2] + p[3])) + (p[4] + p[5]);
        float so = __shfl_xor_sync(FULLMASK, s6, 8);
        // th-symmetric order: both halves compute sum(t0-5) + sum(t6-11)
        float sA = th ? so : s6;
        float sB = th ? s6 : so;
        float inv = __fdividef(1.0f, sA + sB);

        // context partial over this half's 6 timesteps
        float4 c0 = make_float4(0.f, 0.f, 0.f, 0.f);
        float4 c1 = make_float4(0.f, 0.f, 0.f, 0.f);
#pragma unroll
        for (int j = 0; j < 6; j++) {
            c0.x = fmaf(p[j], ev0[j].x, c0.x); c0.y = fmaf(p[j], ev0[j].y, c0.y);
            c0.z = fmaf(p[j], ev0[j].z, c0.z); c0.w = fmaf(p[j], ev0[j].w, c0.w);
            c1.x = fmaf(p[j], ev1[j].x, c1.x); c1.y = fmaf(p[j], ev1[j].y, c1.y);
            c1.z = fmaf(p[j], ev1[j].z, c1.z); c1.w = fmaf(p[j], ev1[j].w, c1.w);
        }
        // cross-half combine (full sum over 12 timesteps)
        c0.x += __shfl_xor_sync(FULLMASK, c0.x, 8);
        c0.y += __shfl_xor_sync(FULLMASK, c0.y, 8);
        c0.z += __shfl_xor_sync(FULLMASK, c0.z, 8);
        c0.w += __shfl_xor_sync(FULLMASK, c0.w, 8);
        c1.x += __shfl_xor_sync(FULLMASK, c1.x, 8);
        c1.y += __shfl_xor_sync(FULLMASK, c1.y, 8);
        c1.z += __shfl_xor_sync(FULLMASK, c1.z, 8);
        c1.w += __shfl_xor_sync(FULLMASK, c1.w, 8);

        h0.x = fmaf(c0.x, inv, h0.x); h0.y = fmaf(c0.y, inv, h0.y);
        h0.z = fmaf(c0.z, inv, h0.z); h0.w = fmaf(c0.w, inv, h0.w);
        h1.x = fmaf(c1.x, inv, h1.x); h1.y = fmaf(c1.y, inv, h1.y);
        h1.z = fmaf(c1.z, inv, h1.z); h1.w = fmaf(c1.w, inv, h1.w);

        if (th == 0) {
            // fp32 hA (for hprev in gates)
            *reinterpret_cast<float4*>(hAsh + bA * HPAD + dl * 8)     = h0;
            *reinterpret_cast<float4*>(hAsh + bA * HPAD + dl * 8 + 4) = h1;
            // half2 A-fragment: 4 consecutive words in array (dl&1)
            *reinterpret_cast<uint4*>(atfdst) =
                make_uint4(packh2(h0.x, h0.y), packh2(h0.z, h0.w),
                           packh2(h1.x, h1.y), packh2(h1.z, h1.w));
        }
        __syncthreads();

        // ---- gate inputs: issue loads early (in flight under MMA)
        float4 Lg0 = Lsh[g];
        float4 Lg8 = Lsh[g + 8];

        // ============ Phase B: gh = hA @ W_hh^T via fp16 MMA ============
        // warp w computes dims 8w..8w+7 for gates r,z,n over all 16 batches.
        float acc[3][4];
#pragma unroll
        for (int gate = 0; gate < 3; gate++)
#pragma unroll
            for (int ci = 0; ci < 4; ci++) acc[gate][ci] = 0.0f;

#pragma unroll
        for (int ktp = 0; ktp < 4; ktp++) {
            int wi = ktp * 4 + t4;
            unsigned a0 = atf0w[g * APW + wi];
            unsigned a1 = atf0w[(g + 8) * APW + wi];
            unsigned a2 = atf1w[g * APW + wi];
            unsigned a3 = atf1w[(g + 8) * APW + wi];
#pragma unroll
            for (int gate = 0; gate < 3; gate++)
                mma_f16(acc[gate][0], acc[gate][1], acc[gate][2], acc[gate][3],
                        a0, a1, a2, a3, breg[gate][ktp].x, breg[gate][ktp].y);
        }

        // ---- gates: lane covers batches {g, g+8} x dims {8w+2t4, 8w+2t4+1}
#pragma unroll
        for (int d01 = 0; d01 < 2; d01++) {
            int dim = w * 8 + 2 * t4 + d01;
            float4 gpr = gpsh[dim];
            float4 gpz = gpsh[64 + dim];
            float4 gpn = gpsh[128 + dim];
            float bhr = bhsh[dim], bhz = bhsh[64 + dim], bhn = bhsh[128 + dim];
#pragma unroll
            for (int bb = 0; bb < 2; bb++) {
                int bat = g + 8 * bb;
                float4 L = bb ? Lg8 : Lg0;
                int ci = bb * 2 + d01;
                float ghr = acc[0][ci] + bhr;
                float ghz = acc[1][ci] + bhz;
                float ghn = acc[2][ci] + bhn;
                float gir = fmaf(gpr.x, L.x, fmaf(gpr.y, L.y, fmaf(gpr.z, L.z, gpr.w)));
                float giz = fmaf(gpz.x, L.x, fmaf(gpz.y, L.y, fmaf(gpz.z, L.z, gpz.w)));
                float gin = fmaf(gpn.x, L.x, fmaf(gpn.y, L.y, fmaf(gpn.z, L.z, gpn.w)));
                float r = sigf(gir + ghr);
                float z = sigf(giz + ghz);
                float n = tanhfast(fmaf(r, ghn, gin));
                float hprev = hAsh[bat * HPAD + dim];
                hGsh[bat * HPAD + dim] = fmaf(z, hprev - n, n);
            }
        }
        __syncthreads();
    }

    // ---- final output (step T_OUT-1) from hG ----
    {
        float4 h0 = *reinterpret_cast<const float4*>(hGsh + bA * HPAD + dl * 8);
        float4 h1 = *reinterpret_cast<const float4*>(hGsh + bA * HPAD + dl * 8 + 4);
        float4 wl0 = Wl4s[dl * 2];
        float4 wl1 = Wl4s[dl * 2 + 1];
        float o = dot8(h0, wl0, h1, wl1);
        o += __shfl_xor_sync(FULLMASK, o, 4);
        o += __shfl_xor_sync(FULLMASK, o, 2);
        o += __shfl_xor_sync(FULLMASK, o, 1);
        o += bl;
        if (l16 == 0) out[gbA * T_OUT + T_OUT - 1] = o;
    }
}

extern "C" void kernel_launch(void* const* d_in, const int* in_sizes, int n_in,
                              void* d_out, int out_size) {
    const float* enc  = (const float*)d_in[0];
    const float* hid0 = (const float*)d_in[1];
    const float* last = (const float*)d_in[2];
    const float* Wih  = (const float*)d_in[3];
    const float* Whh  = (const float*)d_in[4];
    const float* bih  = (const float*)d_in[5];
    const float* bhh  = (const float*)d_in[6];
    const float* Wlin = (const float*)d_in[7];
    const float* blin = (const float*)d_in[8];
    float* out = (float*)d_out;

    cudaFuncSetAttribute(decoder_kernel,
                         cudaFuncAttributeMaxDynamicSharedMemorySize,
                         SMEM_BYTES);

    dim3 grid(Bz / BPC);   // 4096 CTAs of 256 threads
    decoder_kernel<<<grid, THREADS, SMEM_BYTES>>>(
        enc, hid0, last, Wih, Whh, bih, bhh, Wlin, blin, out);
}

// round 17
// speedup vs baseline: 1.3020x; 1.0455x over previous
#include <cuda_runtime.h>
#include <cuda_fp16.h>

// Decoder: T_IN=12, B=65536, H=64, T_OUT=12, OVERLAP=3
// 256 threads / 16 batches per CTA, 2 CTAs/SM (4 warps/SMSP).
//   Phase A (t-split): lane = 8*th + dl within a 16-lane batch group;
//     lane owns dims [8dl,8dl+8) x timesteps [6th,6th+6).
//   Phase B: fp16 mma.sync.m16n8k16.f32 — warp w owns dims 8w..8w+7 for
//     gates r,z,n. B-fragments register-resident (24 regs, loaded once).
//   Hidden state: ONE in-place buffer, swizzled (pitch 72, +4 for dims>=32)
//     -> conflict-free Phase A loads/stores. hprev == post-attention h, so
//     the epilogue reads and overwrites the same buffer (barrier-protected).
// gh MMA inputs/order identical to R13-R15 (bit-identical matvec numerics).

#define FULLMASK 0xFFFFFFFFu

constexpr int T_IN  = 12;
constexpr int T_OUT = 12;
constexpr int Bz    = 65536;
constexpr int WARPS = 8;
constexpr int THREADS = WARPS * 32;
constexpr int BPC   = 16;            // batches per CTA
constexpr int HP    = 72;            // h buffer pitch (floats), swizzled rows
constexpr int APW   = 36;            // A-array per-batch pitch in 32-bit words

// SMEM word offsets
constexpr int OFF_ATF0  = 0;
constexpr int OFF_ATF1  = OFF_ATF0 + BPC * APW;   // 576
constexpr int OFF_H     = OFF_ATF1 + BPC * APW;   // 1152
constexpr int OFF_L     = OFF_H + BPC * HP;       // 2304
constexpr int OFF_GP    = OFF_L + BPC * 4;        // 2368
constexpr int OFF_BN    = OFF_GP + 192 * 4;       // 3136  (bhh for n-gate rows)
constexpr int OFF_WL    = OFF_BN + 64;            // 3200
constexpr int SMEM_FLOATS = OFF_WL + 64;          // 3264
constexpr int SMEM_BYTES  = SMEM_FLOATS * 4;      // 13,056 B

__device__ __forceinline__ unsigned packh2(float lo, float hi) {
    __half2 h = __floats2half2_rn(lo, hi);
    return *reinterpret_cast<unsigned*>(&h);
}
__device__ __forceinline__ void mma_f16(float& d0, float& d1, float& d2, float& d3,
                                        unsigned a0, unsigned a1, unsigned a2, unsigned a3,
                                        unsigned b0, unsigned b1) {
    asm("mma.sync.aligned.m16n8k16.row.col.f32.f16.f16.f32 "
        "{%0,%1,%2,%3}, {%4,%5,%6,%7}, {%8,%9}, {%0,%1,%2,%3};"
        : "+f"(d0), "+f"(d1), "+f"(d2), "+f"(d3)
        : "r"(a0), "r"(a1), "r"(a2), "r"(a3), "r"(b0), "r"(b1));
}
__device__ __forceinline__ float sigf(float x) {
    return __fdividef(1.0f, 1.0f + __expf(-x));
}
__device__ __forceinline__ float tanhfast(float x) {
    return __fdividef(2.0f, 1.0f + __expf(-2.0f * x)) - 1.0f;
}
__device__ __forceinline__ float dot8(float4 a, float4 b, float4 c, float4 d) {
    float s = a.x * b.x;
    s = fmaf(a.y, b.y, s); s = fmaf(a.z, b.z, s); s = fmaf(a.w, b.w, s);
    s = fmaf(c.x, d.x, s); s = fmaf(c.y, d.y, s);
    s = fmaf(c.z, d.z, s); s = fmaf(c.w, d.w, s);
    return s;
}

__global__ void __launch_bounds__(THREADS, 2)
decoder_kernel(const float* __restrict__ enc,    // (12, B, 64)
               const float* __restrict__ hid0,   // (B, 64)
               const float* __restrict__ last,   // (B, 3)
               const float* __restrict__ Wih,    // (192, 3)
               const float* __restrict__ Whh,    // (192, 64)
               const float* __restrict__ bih,    // (192)
               const float* __restrict__ bhh,    // (192)
               const float* __restrict__ Wlin,   // (1, 64)
               const float* __restrict__ blin,   // (1)
               float* __restrict__ out)          // (B, 12)
{
    extern __shared__ float smem[];
    unsigned* atf0w = reinterpret_cast<unsigned*>(smem + OFF_ATF0);
    unsigned* atf1w = reinterpret_cast<unsigned*>(smem + OFF_ATF1);
    float*  hbuf = smem + OFF_H;
    float4* Lsh  = reinterpret_cast<float4*>(smem + OFF_L);
    float4* gpsh = reinterpret_cast<float4*>(smem + OFF_GP);   // {wih0,1,2,bias}
    float*  bnsh = smem + OFF_BN;     // bhh for n-gate rows (j in [128,192))
    float*  wlsh = smem + OFF_WL;

    const int tid  = threadIdx.x;
    const int lane = tid & 31;
    const int w    = tid >> 5;
    const int cb0  = blockIdx.x * BPC;

    // ---- B-fragments of W_hh: REGISTER-RESIDENT, loaded once ----
    uint2 breg[3][4];
    {
        int j0 = w * 8 + (lane >> 2);
        int c0 = 2 * (lane & 3);
#pragma unroll
        for (int gate = 0; gate < 3; gate++) {
            const float* row = Whh + (gate * 64 + j0) * 64;
#pragma unroll
            for (int ktp = 0; ktp < 4; ktp++) {
                int k0 = ktp * 16 + c0;
                breg[gate][ktp] = make_uint2(
                    packh2(__ldg(&row[k0]),     __ldg(&row[k0 + 1])),
                    packh2(__ldg(&row[k0 + 8]), __ldg(&row[k0 + 9])));
            }
        }
    }
    // ---- stage params (bias of r,z gates pre-summed with bhh) ----
    for (int j = tid; j < 192; j += THREADS) {
        float bias = __ldg(&bih[j]) + (j < 128 ? __ldg(&bhh[j]) : 0.0f);
        gpsh[j] = make_float4(__ldg(&Wih[j * 3 + 0]), __ldg(&Wih[j * 3 + 1]),
                              __ldg(&Wih[j * 3 + 2]), bias);
        if (j >= 128) bnsh[j - 128] = __ldg(&bhh[j]);
    }
    if (tid < 64) wlsh[tid] = __ldg(&Wlin[tid]);
    // ---- stage h = hid0 into swizzled rows, Lsh = last ----
    {
        const float4* hid04 = reinterpret_cast<const float4*>(hid0);
        float4* h4 = reinterpret_cast<float4*>(hbuf);
        for (int i = tid; i < BPC * 16; i += THREADS) {
            int b = i >> 4, c = i & 15;
            h4[b * (HP / 4) + c + (c >> 3)] = __ldg(&hid04[(cb0 + b) * 16 + c]);
        }
    }
    if (tid < BPC) {
        int gb = cb0 + tid;
        Lsh[tid] = make_float4(__ldg(&last[gb * 3 + 0]),
                               __ldg(&last[gb * 3 + 1]),
                               __ldg(&last[gb * 3 + 2]), 0.0f);
    }

    // ---- Phase A identity: lane = 16*sub + 8*th + dl
    const int sub = lane >> 4;
    const int l16 = lane & 15;
    const int th  = l16 >> 3;       // timestep half: t = 6*th .. 6*th+5
    const int dl  = l16 & 7;        // dim lane: dims 8*dl .. 8*dl+7
    const int bA  = w * 2 + sub;
    const int gbA = cb0 + bA;
    const float bl = __ldg(blin);
    const float4* Wl4s = reinterpret_cast<const float4*>(wlsh);

    // swizzled h base for this lane's 8 dims
    float* hrow = hbuf + bA * HP + dl * 8 + ((dl >> 2) << 2);

    // atf store target (th==0 lanes only): array (dl&1), word base
    unsigned* atfdst = ((dl & 1) ? atf1w : atf0w) + bA * APW + (dl >> 1) * 4;

    // encoder slice: 6 timesteps x 8 dims
    const float4* enc4 = reinterpret_cast<const float4*>(enc);
    float4 ev0[6], ev1[6];
#pragma unroll
    for (int j = 0; j < 6; j++) {
        int t = 6 * th + j;
        int idx = (t * Bz + gbA) * 16 + dl * 2;
        ev0[j] = __ldg(&enc4[idx]);
        ev1[j] = __ldg(&enc4[idx + 1]);
    }

    // ---- Phase B identity: MMA fragment coords
    const int g  = lane >> 2;     // groupID 0..7 (batch rows g, g+8)
    const int t4 = lane & 3;      // threadID-in-group

    __syncthreads();

#pragma unroll 1
    for (int step = 0; step < T_OUT; step++) {
        // ================= Phase A: out(step-1) + attention =================
        float4 h0 = *reinterpret_cast<const float4*>(hrow);
        float4 h1 = *reinterpret_cast<const float4*>(hrow + 4);

        if (step > 0) {
            float4 wl0 = Wl4s[dl * 2];
            float4 wl1 = Wl4s[dl * 2 + 1];
            float o = dot8(h0, wl0, h1, wl1);
            o += __shfl_xor_sync(FULLMASK, o, 4);
            o += __shfl_xor_sync(FULLMASK, o, 2);
            o += __shfl_xor_sync(FULLMASK, o, 1);
            o += bl;
            if (l16 == 0) {
                float4 L = Lsh[bA];
                out[gbA * T_OUT + step - 1] = o;
                Lsh[bA] = make_float4(o, L.x, L.y, 0.0f);
            }
        }

        // logits for this half's 6 timesteps (partial over 8 dims -> full)
        float p[6];
#pragma unroll
        for (int j = 0; j < 6; j++)
            p[j] = dot8(ev0[j], h0, ev1[j], h1);
#pragma unroll
        for (int off = 4; off > 0; off >>= 1)
#pragma unroll
            for (int j = 0; j < 6; j++)
                p[j] += __shfl_xor_sync(FULLMASK, p[j], off);

        // global max over 12 logits (local 6 + cross-half)
        float m6 = fmaxf(fmaxf(fmaxf(p[0], p[1]), fmaxf(p[2], p[3])),
                         fmaxf(p[4], p[5]));
        float mo = __shfl_xor_sync(FULLMASK, m6, 8);
        float m  = fmaxf(m6, mo);

#pragma unroll
        for (int j = 0; j < 6; j++) p[j] = __expf(p[j] - m);
        float s6 = ((p[0] + p[1]) + (p[2] + p[3])) + (p[4] + p[5]);
        float so = __shfl_xor_sync(FULLMASK, s6, 8);
        // th-symmetric order: both halves compute sum(t0-5) + sum(t6-11)
        float sA = th ? so : s6;
        float sB = th ? s6 : so;
        float inv = __fdividef(1.0f, sA + sB);

        // context partial over this half's 6 timesteps
        float4 c0 = make_float4(0.f, 0.f, 0.f, 0.f);
        float4 c1 = make_float4(0.f, 0.f, 0.f, 0.f);
#pragma unroll
        for (int j = 0; j < 6; j++) {
            c0.x = fmaf(p[j], ev0[j].x, c0.x); c0.y = fmaf(p[j], ev0[j].y, c0.y);
            c0.z = fmaf(p[j], ev0[j].z, c0.z); c0.w = fmaf(p[j], ev0[j].w, c0.w);
            c1.x = fmaf(p[j], ev1[j].x, c1.x); c1.y = fmaf(p[j], ev1[j].y, c1.y);
            c1.z = fmaf(p[j], ev1[j].z, c1.z); c1.w = fmaf(p[j], ev1[j].w, c1.w);
        }
        // cross-half combine (full sum over 12 timesteps)
        c0.x += __shfl_xor_sync(FULLMASK, c0.x, 8);
        c0.y += __shfl_xor_sync(FULLMASK, c0.y, 8);
        c0.z += __shfl_xor_sync(FULLMASK, c0.z, 8);
        c0.w += __shfl_xor_sync(FULLMASK, c0.w, 8);
        c1.x += __shfl_xor_sync(FULLMASK, c1.x, 8);
        c1.y += __shfl_xor_sync(FULLMASK, c1.y, 8);
        c1.z += __shfl_xor_sync(FULLMASK, c1.z, 8);
        c1.w += __shfl_xor_sync(FULLMASK, c1.w, 8);

        h0.x = fmaf(c0.x, inv, h0.x); h0.y = fmaf(c0.y, inv, h0.y);
        h0.z = fmaf(c0.z, inv, h0.z); h0.w = fmaf(c0.w, inv, h0.w);
        h1.x = fmaf(c1.x, inv, h1.x); h1.y = fmaf(c1.y, inv, h1.y);
        h1.z = fmaf(c1.z, inv, h1.z); h1.w = fmaf(c1.w, inv, h1.w);

        if (th == 0) {
            // in-place update: buffer now holds post-attention h (= hprev)
            *reinterpret_cast<float4*>(hrow)     = h0;
            *reinterpret_cast<float4*>(hrow + 4) = h1;
            // half2 A-fragment: 4 consecutive words in array (dl&1)
            *reinterpret_cast<uint4*>(atfdst) =
                make_uint4(packh2(h0.x, h0.y), packh2(h0.z, h0.w),
                           packh2(h1.x, h1.y), packh2(h1.z, h1.w));
        }
        __syncthreads();

        // ---- gate inputs: issue loads early (in flight under MMA)
        float4 Lg0 = Lsh[g];
        float4 Lg8 = Lsh[g + 8];

        // ============ Phase B: gh = hA @ W_hh^T via fp16 MMA ============
        float acc[3][4];
#pragma unroll
        for (int gate = 0; gate < 3; gate++)
#pragma unroll
            for (int ci = 0; ci < 4; ci++) acc[gate][ci] = 0.0f;

#pragma unroll
        for (int ktp = 0; ktp < 4; ktp++) {
            int wi = ktp * 4 + t4;
            unsigned a0 = atf0w[g * APW + wi];
            unsigned a1 = atf0w[(g + 8) * APW + wi];
            unsigned a2 = atf1w[g * APW + wi];
            unsigned a3 = atf1w[(g + 8) * APW + wi];
#pragma unroll
            for (int gate = 0; gate < 3; gate++)
                mma_f16(acc[gate][0], acc[gate][1], acc[gate][2], acc[gate][3],
                        a0, a1, a2, a3, breg[gate][ktp].x, breg[gate][ktp].y);
        }

        // ---- gates: lane covers batches {g, g+8} x dims {8w+2t4, 8w+2t4+1}
#pragma unroll
        for (int d01 = 0; d01 < 2; d01++) {
            int dim = w * 8 + 2 * t4 + d01;
            int physd = dim + ((w >> 2) << 2);   // swizzled column
            float4 gpr = gpsh[dim];
            float4 gpz = gpsh[64 + dim];
            float4 gpn = gpsh[128 + dim];
            float bhn = bnsh[dim];
#pragma unroll
            for (int bb = 0; bb < 2; bb++) {
                int bat = g + 8 * bb;
                float4 L = bb ? Lg8 : Lg0;
                int ci = bb * 2 + d01;
                // r,z: bih+bhh folded into gpr.w / gpz.w
                float gr = fmaf(gpr.x, L.x, fmaf(gpr.y, L.y, fmaf(gpr.z, L.z, gpr.w)))
                         + acc[0][ci];
                float gz = fmaf(gpz.x, L.x, fmaf(gpz.y, L.y, fmaf(gpz.z, L.z, gpz.w)))
                         + acc[1][ci];
                float gin = fmaf(gpn.x, L.x, fmaf(gpn.y, L.y, fmaf(gpn.z, L.z, gpn.w)));
                float ghn = acc[2][ci] + bhn;
                float r = sigf(gr);
                float z = sigf(gz);
                float n = tanhfast(fmaf(r, ghn, gin));
                float* hp = hbuf + bat * HP + physd;
                float hprev = *hp;
                *hp = fmaf(z, hprev - n, n);
            }
        }
        __syncthreads();
    }

    // ---- final output (step T_OUT-1) ----
    {
        float4 h0 = *reinterpret_cast<const float4*>(hrow);
        float4 h1 = *reinterpret_cast<const float4*>(hrow + 4);
        float4 wl0 = Wl4s[dl * 2];
        float4 wl1 = Wl4s[dl * 2 + 1];
        float o = dot8(h0, wl0, h1, wl1);
        o += __shfl_xor_sync(FULLMASK, o, 4);
        o += __shfl_xor_sync(FULLMASK, o, 2);
        o += __shfl_xor_sync(FULLMASK, o, 1);
        o += bl;
        if (l16 == 0) out[gbA * T_OUT + T_OUT - 1] = o;
    }
}

extern "C" void kernel_launch(void* const* d_in, const int* in_sizes, int n_in,
                              void* d_out, int out_size) {
    const float* enc  = (const float*)d_in[0];
    const float* hid0 = (const float*)d_in[1];
    const float* last = (const float*)d_in[2];
    const float* Wih  = (const float*)d_in[3];
    const float* Whh  = (const float*)d_in[4];
    const float* bih  = (const float*)d_in[5];
    const float* bhh  = (const float*)d_in[6];
    const float* Wlin = (const float*)d_in[7];
    const float* blin = (const float*)d_in[8];
    float* out = (float*)d_out;

    cudaFuncSetAttribute(decoder_kernel,
                         cudaFuncAttributeMaxDynamicSharedMemorySize,
                         SMEM_BYTES);

    dim3 grid(Bz / BPC);   // 4096 CTAs of 256 threads
    decoder_kernel<<<grid, THREADS, SMEM_BYTES>>>(
        enc, hid0, last, Wih, Whh, bih, bhh, Wlin, blin, out);
}